// round 5
// baseline (speedup 1.0000x reference)
#include <cuda_runtime.h>

#define M_ROWS 16384
#define NCOL   32
#define NB     128      // gram blocks / partials
#define TILE   128      // rows per gram block
#define EPSV   1e-10f

__device__ __align__(16) float2 g_partial[NB][NCOL * NCOL];
__device__ __align__(16) float2 g_T[NCOL * NCOL];
__device__ int g_ctr;   // zero-init at load; self-resetting each launch

// ---------------------------------------------------------------------------
// K1 (fused): per-block partial Gram; the LAST block to finish reduces all
// partials, runs Cholesky (EPS on diagonal) + upper-triangular inverse, and
// writes T = R^{-1}.  Deterministic: reduction order is a fixed loop; the
// identity of the last block doesn't affect arithmetic.
// ---------------------------------------------------------------------------
__global__ __launch_bounds__(256) void k_fused(const float2* __restrict__ x) {
    __shared__ __align__(16) char sbuf[32768];   // overlaid: xs | Gs/Rs/Ss
    __shared__ int is_last;
    int tid = threadIdx.x;

    // ---- phase 1: stage 128x32 tile, compute 2x2 gram tiles ----
    {
        float2 (*xs)[NCOL] = (float2(*)[NCOL])sbuf;
        const float4* src = (const float4*)(x + (size_t)blockIdx.x * TILE * NCOL);
        float4* dst = (float4*)sbuf;
#pragma unroll
        for (int t = 0; t < 8; t++) dst[tid + 256 * t] = src[tid + 256 * t];
        __syncthreads();

        int i0 = (tid >> 4) << 1;
        int j0 = (tid & 15) << 1;
        float a00x = 0.f, a00y = 0.f, a01x = 0.f, a01y = 0.f;
        float a10x = 0.f, a10y = 0.f, a11x = 0.f, a11y = 0.f;
#pragma unroll 8
        for (int m = 0; m < TILE; m++) {
            float4 av = *(const float4*)&xs[m][i0];
            float4 bv = *(const float4*)&xs[m][j0];
            a00x += av.x * bv.x + av.y * bv.y;  a00y += av.x * bv.y - av.y * bv.x;
            a01x += av.x * bv.z + av.y * bv.w;  a01y += av.x * bv.w - av.y * bv.z;
            a10x += av.z * bv.x + av.w * bv.y;  a10y += av.z * bv.y - av.w * bv.x;
            a11x += av.z * bv.z + av.w * bv.w;  a11y += av.z * bv.w - av.w * bv.z;
        }
        float2* out = g_partial[blockIdx.x];
        out[i0 * 32 + j0]           = make_float2(a00x, a00y);
        out[i0 * 32 + j0 + 1]       = make_float2(a01x, a01y);
        out[(i0 + 1) * 32 + j0]     = make_float2(a10x, a10y);
        out[(i0 + 1) * 32 + j0 + 1] = make_float2(a11x, a11y);
    }

    __threadfence();                         // release partials
    if (tid == 0) is_last = (atomicAdd(&g_ctr, 1) == NB - 1);
    __syncthreads();
    if (!is_last) return;
    if (tid == 0) g_ctr = 0;                 // reset for next graph replay
    __threadfence();                         // acquire partials

    // ---- phase 2 (last block only): reduce partials into Gs ----
    float2 (*Gs)[NCOL] = (float2(*)[NCOL])sbuf;
    float2 (*Rs)[NCOL] = (float2(*)[NCOL])(sbuf + 8192);
    float2 (*Ss)[NCOL] = (float2(*)[NCOL])(sbuf + 16384);
    __syncthreads();                         // everyone done with xs
    {
        float2 acc0 = make_float2(0.f, 0.f), acc1 = acc0, acc2 = acc0, acc3 = acc0;
#pragma unroll 4
        for (int b = 0; b < NB; b++) {
            float2 p0 = g_partial[b][tid];
            float2 p1 = g_partial[b][tid + 256];
            float2 p2 = g_partial[b][tid + 512];
            float2 p3 = g_partial[b][tid + 768];
            acc0.x += p0.x; acc0.y += p0.y;
            acc1.x += p1.x; acc1.y += p1.y;
            acc2.x += p2.x; acc2.y += p2.y;
            acc3.x += p3.x; acc3.y += p3.y;
        }
        int e0 = tid, e1 = tid + 256, e2 = tid + 512, e3 = tid + 768;
        Gs[e0 >> 5][e0 & 31] = acc0;
        Gs[e1 >> 5][e1 & 31] = acc1;
        Gs[e2 >> 5][e2 & 31] = acc2;
        Gs[e3 >> 5][e3 & 31] = acc3;
    }
    __syncthreads();

    // ---- phase 3: Cholesky (upper), warp 0, lane = column k ----
    if (tid < 32) {
        int k = tid;
        for (int j = 0; j < 32; j++) {
            float2 acc = Gs[j][k];
            for (int i = 0; i < j; i++) {
                float2 rij = Rs[i][j];
                float2 rik = Rs[i][k];
                acc.x -= rij.x * rik.x + rij.y * rik.y;   // conj(rij)*rik
                acc.y -= rij.x * rik.y - rij.y * rik.x;
            }
            float djj = __shfl_sync(0xffffffffu, acc.x, j);
            float rjj = sqrtf(djj + EPSV);
            float inv = 1.0f / rjj;
            float2 out;
            if (k < j)       out = make_float2(0.f, 0.f);
            else if (k == j) out = make_float2(rjj, 0.f);
            else             out = make_float2(acc.x * inv, acc.y * inv);
            Rs[j][k] = out;
            __syncwarp();
        }
    }
    __syncthreads();

    // ---- phase 4: S = R^{-1} (upper). Thread j owns column j. ----
    if (tid < 32) {
        int j = tid;
        Ss[j][j] = make_float2(1.0f / Rs[j][j].x, 0.f);
        for (int i = j - 1; i >= 0; i--) {
            float ax = 0.f, ay = 0.f;
            for (int k = i + 1; k <= j; k++) {
                float2 rv = Rs[i][k];
                float2 sv = Ss[k][j];
                ax += rv.x * sv.x - rv.y * sv.y;
                ay += rv.x * sv.y + rv.y * sv.x;
            }
            float inv = 1.0f / Rs[i][i].x;
            Ss[i][j] = make_float2(-ax * inv, -ay * inv);
        }
    }
    __syncthreads();

    // ---- phase 5: write T (lower triangle = 0; Ss lower is uninitialized) ----
    for (int t = tid; t < 1024; t += 256) {
        int r = t >> 5, c = t & 31;
        g_T[t] = (r <= c) ? Ss[r][c] : make_float2(0.f, 0.f);
    }
}

// ---------------------------------------------------------------------------
// K2: Y = X * T.  1024 blocks x 128 threads, 16 rows/block, 4 rows/thread.
// T in split real/imag float planes (conflict-free LDS.32); x via LDS.128.
// ---------------------------------------------------------------------------
__global__ __launch_bounds__(128) void k_apply(const float2* __restrict__ x,
                                               float2* __restrict__ y) {
    __shared__ __align__(16) float2 xs[16][NCOL];   // 4KB
    __shared__ float Tre[32][32];                   // 4KB
    __shared__ float Tim[32][32];                   // 4KB
    int tid = threadIdx.x;

    // stage x: 16 rows x 32 cols = 256 float4, 2 per thread
    const float4* xsrc = (const float4*)(x + (size_t)blockIdx.x * 16 * NCOL);
    float4* xdst = (float4*)&xs[0][0];
    xdst[tid]       = xsrc[tid];
    xdst[tid + 128] = xsrc[tid + 128];
    // stage T split planes: 8 per thread
#pragma unroll
    for (int t = tid; t < 1024; t += 128) {
        float2 v = g_T[t];
        Tre[t >> 5][t & 31] = v.x;
        Tim[t >> 5][t & 31] = v.y;
    }
    __syncthreads();

    int j = tid & 31;
    int r0 = (tid >> 5) * 4;   // 4 rows per thread

    float ax[4], ay[4];
#pragma unroll
    for (int r = 0; r < 4; r++) { ax[r] = 0.f; ay[r] = 0.f; }

#pragma unroll
    for (int k = 0; k < 32; k += 2) {
        float tr0 = Tre[k][j],     ti0 = Tim[k][j];
        float tr1 = Tre[k + 1][j], ti1 = Tim[k + 1][j];
#pragma unroll
        for (int r = 0; r < 4; r++) {
            float4 a = *(const float4*)&xs[r0 + r][k];   // (xk.re,xk.im,xk1.re,xk1.im)
            ax[r] += a.x * tr0 - a.y * ti0;
            ay[r] += a.x * ti0 + a.y * tr0;
            ax[r] += a.z * tr1 - a.w * ti1;
            ay[r] += a.z * ti1 + a.w * tr1;
        }
    }

    size_t base = (size_t)blockIdx.x * 16;
#pragma unroll
    for (int r = 0; r < 4; r++) {
        y[(base + r0 + r) * NCOL + j] = make_float2(ax[r], ay[r]);
    }
}

// ---------------------------------------------------------------------------
extern "C" void kernel_launch(void* const* d_in, const int* in_sizes, int n_in,
                              void* d_out, int out_size) {
    const float2* x = (const float2*)d_in[0];
    float2* y = (float2*)d_out;
    (void)in_sizes; (void)n_in; (void)out_size;

    k_fused<<<NB, 256>>>(x);
    k_apply<<<M_ROWS / 16, 128>>>(x, y);
}

// round 6
// speedup vs baseline: 1.1575x; 1.1575x over previous
#include <cuda_runtime.h>

#define M_ROWS 16384
#define NCOL   32
#define NB     128      // gram blocks / partials
#define TILE   128      // rows per gram block
#define EPSV   1e-10f

__device__ __align__(16) float2 g_partial[NB][NCOL * NCOL];
__device__ __align__(16) float2 g_T[NCOL * NCOL];

// ---------------------------------------------------------------------------
// K1: per-block partial Gram.  G[i][j] = sum_m conj(x[m][i]) * x[m][j]
// 256 threads, each owns a 2x2 (i,j) tile.
// ---------------------------------------------------------------------------
__global__ __launch_bounds__(256) void k_gram(const float2* __restrict__ x) {
    __shared__ __align__(16) float2 xs[TILE][NCOL];
    int tid = threadIdx.x;
    const float4* src = (const float4*)(x + (size_t)blockIdx.x * TILE * NCOL);
    float4* dst = (float4*)&xs[0][0];
#pragma unroll
    for (int t = 0; t < 8; t++) dst[tid + 256 * t] = src[tid + 256 * t];
    __syncthreads();

    int i0 = (tid >> 4) << 1;
    int j0 = (tid & 15) << 1;
    float a00x = 0.f, a00y = 0.f, a01x = 0.f, a01y = 0.f;
    float a10x = 0.f, a10y = 0.f, a11x = 0.f, a11y = 0.f;
#pragma unroll 8
    for (int m = 0; m < TILE; m++) {
        float4 av = *(const float4*)&xs[m][i0];
        float4 bv = *(const float4*)&xs[m][j0];
        a00x += av.x * bv.x + av.y * bv.y;  a00y += av.x * bv.y - av.y * bv.x;
        a01x += av.x * bv.z + av.y * bv.w;  a01y += av.x * bv.w - av.y * bv.z;
        a10x += av.z * bv.x + av.w * bv.y;  a10y += av.z * bv.y - av.w * bv.x;
        a11x += av.z * bv.z + av.w * bv.w;  a11y += av.z * bv.w - av.w * bv.z;
    }
    float2* out = g_partial[blockIdx.x];
    out[i0 * 32 + j0]           = make_float2(a00x, a00y);
    out[i0 * 32 + j0 + 1]       = make_float2(a01x, a01y);
    out[(i0 + 1) * 32 + j0]     = make_float2(a10x, a10y);
    out[(i0 + 1) * 32 + j0 + 1] = make_float2(a11x, a11y);
}

// ---------------------------------------------------------------------------
// K2: 1024-thread: high-MLP reduce of 128 partials -> G, then serial
// Cholesky (warp 0) + parallel-column triangular inverse -> T = R^{-1}.
// ---------------------------------------------------------------------------
__global__ __launch_bounds__(1024) void k_small() {
    __shared__ float2 Gs[32][32];
    __shared__ float2 Rs[32][32];
    __shared__ float2 Ss[32][32];
    __shared__ float  invd[32];
    __shared__ __align__(16) float4 red[512];
    int tid = threadIdx.x;
    int e = tid & 511;                       // float4 element index (0..511)

    // ---- reduce: halves of the partial list on thread halves, float4 lanes ----
    const float4* gp = (const float4*)g_partial;   // 128 partials x 512 float4
    float4 acc = make_float4(0.f, 0.f, 0.f, 0.f);
    if (tid < 512) {
#pragma unroll 16
        for (int b = 0; b < 64; b++) {
            float4 p = gp[b * 512 + e];
            acc.x += p.x; acc.y += p.y; acc.z += p.z; acc.w += p.w;
        }
    } else {
#pragma unroll 16
        for (int b = 64; b < 128; b++) {
            float4 p = gp[b * 512 + e];
            acc.x += p.x; acc.y += p.y; acc.z += p.z; acc.w += p.w;
        }
        red[e] = acc;
    }
    __syncthreads();
    if (tid < 512) {
        float4 o = red[e];
        acc.x += o.x; acc.y += o.y; acc.z += o.z; acc.w += o.w;
        int r = e >> 4;
        int c = (e & 15) * 2;
        Gs[r][c]     = make_float2(acc.x, acc.y);
        Gs[r][c + 1] = make_float2(acc.z, acc.w);
    }
    // zero R upper-left state
    if (tid < 1024) {
        int r = tid >> 5, c = tid & 31;
        Rs[r][c] = make_float2(0.f, 0.f);
    }
    __syncthreads();

    // ---- Cholesky (upper), warp 0, lane = column k ----
    if (tid < 32) {
        int k = tid;
        for (int j = 0; j < 32; j++) {
            float2 a = Gs[j][k];
            for (int i = 0; i < j; i++) {
                float2 rij = Rs[i][j];
                float2 rik = Rs[i][k];
                a.x -= rij.x * rik.x + rij.y * rik.y;   // conj(rij)*rik
                a.y -= rij.x * rik.y - rij.y * rik.x;
            }
            float djj = __shfl_sync(0xffffffffu, a.x, j);
            float rjj = sqrtf(djj + EPSV);
            float inv = 1.0f / rjj;
            float2 out;
            if (k < j)       out = make_float2(0.f, 0.f);
            else if (k == j) out = make_float2(rjj, 0.f);
            else             out = make_float2(a.x * inv, a.y * inv);
            Rs[j][k] = out;
            __syncwarp();
        }
        invd[k] = 1.0f / Rs[k][k].x;         // after loop: diag final
    }
    __syncthreads();

    // ---- S = R^{-1} (upper). Thread j owns column j; invd precomputed. ----
    if (tid < 32) {
        int j = tid;
        Ss[j][j] = make_float2(invd[j], 0.f);
        for (int i = j - 1; i >= 0; i--) {
            float ax = 0.f, ay = 0.f;
            for (int k = i + 1; k <= j; k++) {
                float2 rv = Rs[i][k];
                float2 sv = Ss[k][j];
                ax += rv.x * sv.x - rv.y * sv.y;
                ay += rv.x * sv.y + rv.y * sv.x;
            }
            float inv = invd[i];
            Ss[i][j] = make_float2(-ax * inv, -ay * inv);
        }
    }
    __syncthreads();

    // ---- write T (lower triangle = 0) ----
    {
        int r = tid >> 5, c = tid & 31;
        g_T[tid] = (r <= c) ? Ss[r][c] : make_float2(0.f, 0.f);
    }
}

// ---------------------------------------------------------------------------
// K3: Y = X * T.  1024 blocks x 256 threads, 16 rows/block, 2 rows/thread.
// T in split real/imag planes (conflict-free LDS.32); x rows via broadcast
// LDS.128 (whole warp shares its 2 rows).
// ---------------------------------------------------------------------------
__global__ __launch_bounds__(256) void k_apply(const float2* __restrict__ x,
                                               float2* __restrict__ y) {
    __shared__ __align__(16) float2 xs[16][NCOL];   // 4KB
    __shared__ float Tre[32][32];                   // 4KB
    __shared__ float Tim[32][32];                   // 4KB
    int tid = threadIdx.x;

    // stage x: 16 rows x 32 cols = 256 float4, 1 per thread
    const float4* xsrc = (const float4*)(x + (size_t)blockIdx.x * 16 * NCOL);
    ((float4*)&xs[0][0])[tid] = xsrc[tid];
    // stage T split planes: 4 per thread
#pragma unroll
    for (int t = tid; t < 1024; t += 256) {
        float2 v = g_T[t];
        Tre[t >> 5][t & 31] = v.x;
        Tim[t >> 5][t & 31] = v.y;
    }
    __syncthreads();

    int j = tid & 31;
    int r0 = (tid >> 5) * 2;   // 2 rows per thread; uniform per warp

    float ax0 = 0.f, ay0 = 0.f, ax1 = 0.f, ay1 = 0.f;

#pragma unroll
    for (int k = 0; k < 32; k += 2) {
        float tr0 = Tre[k][j],     ti0 = Tim[k][j];
        float tr1 = Tre[k + 1][j], ti1 = Tim[k + 1][j];
        float4 a = *(const float4*)&xs[r0][k];       // row r0, cols k,k+1
        float4 b = *(const float4*)&xs[r0 + 1][k];   // row r0+1
        ax0 += a.x * tr0 - a.y * ti0;  ay0 += a.x * ti0 + a.y * tr0;
        ax0 += a.z * tr1 - a.w * ti1;  ay0 += a.z * ti1 + a.w * tr1;
        ax1 += b.x * tr0 - b.y * ti0;  ay1 += b.x * ti0 + b.y * tr0;
        ax1 += b.z * tr1 - b.w * ti1;  ay1 += b.z * ti1 + b.w * tr1;
    }

    size_t base = (size_t)blockIdx.x * 16 + r0;
    y[base * NCOL + j]       = make_float2(ax0, ay0);
    y[(base + 1) * NCOL + j] = make_float2(ax1, ay1);
}

// ---------------------------------------------------------------------------
extern "C" void kernel_launch(void* const* d_in, const int* in_sizes, int n_in,
                              void* d_out, int out_size) {
    const float2* x = (const float2*)d_in[0];
    float2* y = (float2*)d_out;
    (void)in_sizes; (void)n_in; (void)out_size;

    k_gram <<<NB, 256>>>(x);
    k_small<<<1, 1024>>>();
    k_apply<<<M_ROWS / 16, 256>>>(x, y);
}

// round 7
// speedup vs baseline: 1.3385x; 1.1563x over previous
#include <cuda_runtime.h>

#define NBLK 128
#define TPB  512
#define TILE 128     // rows per block (gram and apply)
#define EPSV 1e-10f

__device__ __align__(16) float2 g_partial[NBLK][1024];
__device__ __align__(16) float2 g_T[1024];
__device__ unsigned g_tickets;   // monotonic across graph replays; never reset

// Replay-safe grid barrier: ticket counter only ever increments.
// Each sync advances the counter by exactly gridDim (=128); a block waits
// until the counter reaches the next multiple of 128 above its own ticket.
__device__ __forceinline__ void grid_sync() {
    __syncthreads();
    if (threadIdx.x == 0) {
        __threadfence();
        unsigned v = atomicAdd(&g_tickets, 1u);
        unsigned target = (v | (NBLK - 1u)) + 1u;
        while ((int)(*(volatile unsigned*)&g_tickets - target) < 0) { }
        __threadfence();
    }
    __syncthreads();
}

__global__ __launch_bounds__(TPB, 1) void k_all(const float2* __restrict__ x,
                                                float2* __restrict__ y) {
    __shared__ __align__(16) char smem[40960];   // 40KB overlay
    int tid = threadIdx.x;
    int blk = blockIdx.x;

    // ================= phase 1: partial Gram =================
    {
        float2 (*xs)[32] = (float2(*)[32])smem;          // 128x32 float2 = 32KB
        const float4* src = (const float4*)(x + (size_t)blk * TILE * 32);
        float4* dst = (float4*)smem;
#pragma unroll
        for (int t = 0; t < 4; t++) dst[tid + TPB * t] = src[tid + TPB * t];  // 2048 float4
        __syncthreads();

        int gid = tid >> 8;          // m-group 0/1 (rows 0-63 / 64-127)
        int t8  = tid & 255;
        int i0 = (t8 >> 4) << 1;
        int j0 = (t8 & 15) << 1;
        int mbase = gid * 64;
        float a00x = 0.f, a00y = 0.f, a01x = 0.f, a01y = 0.f;
        float a10x = 0.f, a10y = 0.f, a11x = 0.f, a11y = 0.f;
#pragma unroll 8
        for (int mm = 0; mm < 64; mm++) {
            float4 av = *(const float4*)&xs[mbase + mm][i0];
            float4 bv = *(const float4*)&xs[mbase + mm][j0];
            a00x += av.x * bv.x + av.y * bv.y;  a00y += av.x * bv.y - av.y * bv.x;
            a01x += av.x * bv.z + av.y * bv.w;  a01y += av.x * bv.w - av.y * bv.z;
            a10x += av.z * bv.x + av.w * bv.y;  a10y += av.z * bv.y - av.w * bv.x;
            a11x += av.z * bv.z + av.w * bv.w;  a11y += av.z * bv.w - av.w * bv.z;
        }
        __syncthreads();                         // all reads of xs done
        float2* pbuf = (float2*)smem;            // 4*256 float2 = 8KB (overlays xs)
        if (gid == 1) {
            pbuf[0 * 256 + t8] = make_float2(a00x, a00y);
            pbuf[1 * 256 + t8] = make_float2(a01x, a01y);
            pbuf[2 * 256 + t8] = make_float2(a10x, a10y);
            pbuf[3 * 256 + t8] = make_float2(a11x, a11y);
        }
        __syncthreads();
        if (gid == 0) {
            float2 q;
            q = pbuf[0 * 256 + t8]; a00x += q.x; a00y += q.y;
            q = pbuf[1 * 256 + t8]; a01x += q.x; a01y += q.y;
            q = pbuf[2 * 256 + t8]; a10x += q.x; a10y += q.y;
            q = pbuf[3 * 256 + t8]; a11x += q.x; a11y += q.y;
            float2* out = g_partial[blk];
            out[i0 * 32 + j0]           = make_float2(a00x, a00y);
            out[i0 * 32 + j0 + 1]       = make_float2(a01x, a01y);
            out[(i0 + 1) * 32 + j0]     = make_float2(a10x, a10y);
            out[(i0 + 1) * 32 + j0 + 1] = make_float2(a11x, a11y);
        }
    }

    grid_sync();

    // ================= phase 2: block 0 reduce + solve =================
    if (blk == 0) {
        float2 (*Gs)[32] = (float2(*)[32])smem;
        float2 (*Rs)[32] = (float2(*)[32])(smem + 8192);
        float2 (*Ss)[32] = (float2(*)[32])(smem + 16384);
        float*  invd     = (float*)(smem + 24576);

        // reduce 128 partials; 512 threads = one float4 lane each, high MLP
        {
            const float4* gp = (const float4*)g_partial;   // 128 x 512 float4
            float4 acc = make_float4(0.f, 0.f, 0.f, 0.f);
#pragma unroll 8
            for (int b = 0; b < NBLK; b++) {
                float4 p = gp[b * 512 + tid];
                acc.x += p.x; acc.y += p.y; acc.z += p.z; acc.w += p.w;
            }
            int r = tid >> 4;
            int c = (tid & 15) * 2;
            Gs[r][c]     = make_float2(acc.x, acc.y);
            Gs[r][c + 1] = make_float2(acc.z, acc.w);
        }
        for (int t = tid; t < 1024; t += TPB) {
            Rs[t >> 5][t & 31] = make_float2(0.f, 0.f);
            Ss[t >> 5][t & 31] = make_float2(0.f, 0.f);
        }
        __syncthreads();

        // Cholesky (upper), warp 0, lane = column k
        if (tid < 32) {
            int k = tid;
            for (int j = 0; j < 32; j++) {
                float2 a = Gs[j][k];
                for (int i = 0; i < j; i++) {
                    float2 rij = Rs[i][j];
                    float2 rik = Rs[i][k];
                    a.x -= rij.x * rik.x + rij.y * rik.y;   // conj(rij)*rik
                    a.y -= rij.x * rik.y - rij.y * rik.x;
                }
                float djj = __shfl_sync(0xffffffffu, a.x, j);
                float rjj = sqrtf(djj + EPSV);
                float inv = 1.0f / rjj;
                float2 out;
                if (k < j)       out = make_float2(0.f, 0.f);
                else if (k == j) out = make_float2(rjj, 0.f);
                else             out = make_float2(a.x * inv, a.y * inv);
                Rs[j][k] = out;
                __syncwarp();
            }
            invd[k] = 1.0f / Rs[k][k].x;
        }
        __syncthreads();

        // S = R^{-1} (upper). Thread j owns column j.
        if (tid < 32) {
            int j = tid;
            Ss[j][j] = make_float2(invd[j], 0.f);
            for (int i = j - 1; i >= 0; i--) {
                float ax = 0.f, ay = 0.f;
                for (int k = i + 1; k <= j; k++) {
                    float2 rv = Rs[i][k];
                    float2 sv = Ss[k][j];
                    ax += rv.x * sv.x - rv.y * sv.y;
                    ay += rv.x * sv.y + rv.y * sv.x;
                }
                float inv = invd[i];
                Ss[i][j] = make_float2(-ax * inv, -ay * inv);
            }
        }
        __syncthreads();

        // write T (lower triangle = 0)
        for (int t = tid; t < 1024; t += TPB) {
            int r = t >> 5, c = t & 31;
            g_T[t] = (r <= c) ? Ss[r][c] : make_float2(0.f, 0.f);
        }
    }

    grid_sync();

    // ================= phase 3: apply  Y = X * T =================
    {
        float2 (*xa)[32] = (float2(*)[32])smem;                    // 32KB
        float (*Tre)[32] = (float(*)[32])(smem + 32768);           // 4KB
        float (*Tim)[32] = (float(*)[32])(smem + 32768 + 4096);    // 4KB

        const float4* xsrc = (const float4*)(x + (size_t)blk * TILE * 32);
        float4* xdst = (float4*)smem;
#pragma unroll
        for (int t = 0; t < 4; t++) xdst[tid + TPB * t] = xsrc[tid + TPB * t];
        for (int t = tid; t < 1024; t += TPB) {
            float2 v = g_T[t];
            Tre[t >> 5][t & 31] = v.x;
            Tim[t >> 5][t & 31] = v.y;
        }
        __syncthreads();

        int j  = tid & 31;
        int r0 = (tid >> 5) * 8;   // 16 warps x 8 rows = 128 rows

        float ax[8], ay[8];
#pragma unroll
        for (int r = 0; r < 8; r++) { ax[r] = 0.f; ay[r] = 0.f; }

#pragma unroll
        for (int k = 0; k < 32; k += 2) {
            float tr0 = Tre[k][j],     ti0 = Tim[k][j];
            float tr1 = Tre[k + 1][j], ti1 = Tim[k + 1][j];
#pragma unroll
            for (int r = 0; r < 8; r++) {
                float4 a = *(const float4*)&xa[r0 + r][k];   // (re_k, im_k, re_k1, im_k1)
                ax[r] += a.x * tr0 - a.y * ti0;
                ay[r] += a.x * ti0 + a.y * tr0;
                ax[r] += a.z * tr1 - a.w * ti1;
                ay[r] += a.z * ti1 + a.w * tr1;
            }
        }

        size_t base = (size_t)blk * TILE + r0;
#pragma unroll
        for (int r = 0; r < 8; r++) {
            y[(base + r) * 32 + j] = make_float2(ax[r], ay[r]);
        }
    }
}

// ---------------------------------------------------------------------------
extern "C" void kernel_launch(void* const* d_in, const int* in_sizes, int n_in,
                              void* d_out, int out_size) {
    const float2* x = (const float2*)d_in[0];
    float2* y = (float2*)d_out;
    (void)in_sizes; (void)n_in; (void)out_size;

    k_all<<<NBLK, TPB>>>(x, y);
}

// round 10
// speedup vs baseline: 1.4637x; 1.0935x over previous
#include <cuda_runtime.h>

#define NBLK 128
#define TPB  512
#define TILE 128
#define EPSV 1e-10f

__device__ __align__(16) float2 g_partial[NBLK][1024];
__device__ __align__(16) float2 g_T[1024];
__device__ unsigned g_arrive;   // monotonic across replays; never reset
__device__ unsigned g_tready;   // monotonic across replays; never reset

__global__ __launch_bounds__(TPB, 1) void k_all(const float2* __restrict__ x,
                                                float2* __restrict__ y) {
    __shared__ __align__(16) char smem[40960];   // [0,32K) xs | [32K,40K) AUX
    __shared__ float invd[32];
    int tid = threadIdx.x;
    int blk = blockIdx.x;

    float2 (*xs)[32] = (float2(*)[32])smem;      // 128 x 32 float2, resident
    char* AUX = smem + 32768;                    // 8KB: pbuf / Rs / Tre+Tim

    // ================= phase 1: stage x tile, Hermitian partial Gram ========
    const float4* src = (const float4*)(x + (size_t)blk * TILE * 32);
    {
        float4* dst = (float4*)smem;
#pragma unroll
        for (int t = 0; t < 4; t++) dst[tid + TPB * t] = src[tid + TPB * t];
    }
    __syncthreads();

    {
        int gid = tid >> 8;          // m-group: rows 0-63 / 64-127
        int t8  = tid & 255;
        bool active = (t8 < 136);    // 136 upper-triangular 2x2 tiles
        int i0 = 0, j0 = 0;
        if (active) {
            int tt = t8, ti = 0;
            while (tt >= 16 - ti) { tt -= 16 - ti; ti++; }
            i0 = ti * 2;
            j0 = (ti + tt) * 2;
        }
        float a00x = 0.f, a00y = 0.f, a01x = 0.f, a01y = 0.f;
        float a10x = 0.f, a10y = 0.f, a11x = 0.f, a11y = 0.f;
        if (active) {
            int mbase = gid * 64;
#pragma unroll 8
            for (int mm = 0; mm < 64; mm++) {
                float4 av = *(const float4*)&xs[mbase + mm][i0];
                float4 bv = *(const float4*)&xs[mbase + mm][j0];
                a00x += av.x * bv.x + av.y * bv.y;  a00y += av.x * bv.y - av.y * bv.x;
                a01x += av.x * bv.z + av.y * bv.w;  a01y += av.x * bv.w - av.y * bv.z;
                a10x += av.z * bv.x + av.w * bv.y;  a10y += av.z * bv.y - av.w * bv.x;
                a11x += av.z * bv.z + av.w * bv.w;  a11y += av.z * bv.w - av.w * bv.z;
            }
        }
        float2* P = (float2*)AUX;    // 4 x 136 float2 combine buffer
        if (gid == 1 && active) {
            P[0 * 136 + t8] = make_float2(a00x, a00y);
            P[1 * 136 + t8] = make_float2(a01x, a01y);
            P[2 * 136 + t8] = make_float2(a10x, a10y);
            P[3 * 136 + t8] = make_float2(a11x, a11y);
        }
        __syncthreads();
        if (gid == 0 && active) {
            float2 q;
            q = P[0 * 136 + t8]; a00x += q.x; a00y += q.y;
            q = P[1 * 136 + t8]; a01x += q.x; a01y += q.y;
            q = P[2 * 136 + t8]; a10x += q.x; a10y += q.y;
            q = P[3 * 136 + t8]; a11x += q.x; a11y += q.y;
            float2* out = g_partial[blk];
            out[i0 * 32 + j0]           = make_float2(a00x, a00y);
            out[i0 * 32 + j0 + 1]       = make_float2(a01x, a01y);
            out[(i0 + 1) * 32 + j0]     = make_float2(a10x, a10y);
            out[(i0 + 1) * 32 + j0 + 1] = make_float2(a11x, a11y);
            // Hermitian mirror: G[j][i] = conj(G[i][j])
            out[j0 * 32 + i0]           = make_float2(a00x, -a00y);
            out[j0 * 32 + i0 + 1]       = make_float2(a10x, -a10y);
            out[(j0 + 1) * 32 + i0]     = make_float2(a01x, -a01y);
            out[(j0 + 1) * 32 + i0 + 1] = make_float2(a11x, -a11y);
        }
    }

    __threadfence();          // release partial stores
    __syncthreads();
    unsigned rep = 0;
    if (tid == 0) {
        unsigned v = atomicAdd(&g_arrive, 1u);
        rep = (v >> 7) + 1u;  // replay index (arrive target = rep*128)
        if (blk == 0) {
            unsigned target = rep << 7;
            while ((int)(*(volatile unsigned*)&g_arrive - target) < 0) { }
            __threadfence();  // acquire partials
        }
    }

    // ================= phase 2: block 0 reduce + solve ======================
    if (blk == 0) {
        __syncthreads();      // whole block waits on thread 0's spin
        // overlays: Gs = xs rows 0..31, Ss = xs rows 32..63, Rs = AUX
        float2 (*Gs)[32] = (float2(*)[32])smem;
        float2 (*Ss)[32] = (float2(*)[32])(smem + 8192);
        float2 (*Rs)[32] = (float2(*)[32])AUX;

        // reduce 128 partials (512 threads = one float4 lane each, high MLP)
        {
            const float4* gp = (const float4*)g_partial;   // 128 x 512 float4
            float4 acc = make_float4(0.f, 0.f, 0.f, 0.f);
#pragma unroll 8
            for (int b = 0; b < NBLK; b++) {
                float4 p = gp[b * 512 + tid];
                acc.x += p.x; acc.y += p.y; acc.z += p.z; acc.w += p.w;
            }
            int r = tid >> 4;
            int c = (tid & 15) * 2;
            Gs[r][c]     = make_float2(acc.x, acc.y);
            Gs[r][c + 1] = make_float2(acc.z, acc.w);
        }
        __syncthreads();

        // Cholesky (upper), warp 0, lane = column k (every row fully written)
        if (tid < 32) {
            int k = tid;
            for (int j = 0; j < 32; j++) {
                float2 a = Gs[j][k];
                for (int i = 0; i < j; i++) {
                    float2 rij = Rs[i][j];
                    float2 rik = Rs[i][k];
                    a.x -= rij.x * rik.x + rij.y * rik.y;   // conj(rij)*rik
                    a.y -= rij.x * rik.y - rij.y * rik.x;
                }
                float djj = __shfl_sync(0xffffffffu, a.x, j);
                float rjj = sqrtf(djj + EPSV);
                float inv = 1.0f / rjj;
                float2 out;
                if (k < j)       out = make_float2(0.f, 0.f);
                else if (k == j) out = make_float2(rjj, 0.f);
                else             out = make_float2(a.x * inv, a.y * inv);
                Rs[j][k] = out;
                __syncwarp();
            }
            invd[k] = 1.0f / Rs[k][k].x;
        }
        __syncthreads();

        // Blocked tri-inverse: S11 (lanes 0-15) and S22 (lanes 16-31) in parallel
        if (tid < 32) {
            int half = tid >> 4;
            int j = tid & 15;
            int base = half * 16;
            int gj = base + j;
            Ss[gj][gj] = make_float2(invd[gj], 0.f);
            for (int i = j - 1; i >= 0; i--) {
                int gi = base + i;
                float ax = 0.f, ay = 0.f;
                for (int k = i + 1; k <= j; k++) {
                    int gk = base + k;
                    float2 rv = Rs[gi][gk];
                    float2 sv = Ss[gk][gj];
                    ax += rv.x * sv.x - rv.y * sv.y;
                    ay += rv.x * sv.y + rv.y * sv.x;
                }
                float inv = invd[gi];
                Ss[gi][gj] = make_float2(-ax * inv, -ay * inv);
            }
        }
        __syncthreads();

        // Tmp = R12 * S22  (into Gs region, free after chol)
        // S22 is upper-triangular: only k <= j entries of Ss[16+k][16+j] exist.
        float2 (*Tmp)[16] = (float2(*)[16])smem;
        if (tid < 256) {
            int i = tid >> 4, j = tid & 15;
            float ax = 0.f, ay = 0.f;
            for (int k = 0; k <= j; k++) {
                float2 rv = Rs[i][16 + k];
                float2 sv = Ss[16 + k][16 + j];
                ax += rv.x * sv.x - rv.y * sv.y;
                ay += rv.x * sv.y + rv.y * sv.x;
            }
            Tmp[i][j] = make_float2(ax, ay);
        }
        __syncthreads();
        // S12 = -S11 * Tmp   (S11 upper-triangular: k >= i)
        if (tid < 256) {
            int i = tid >> 4, j = tid & 15;
            float ax = 0.f, ay = 0.f;
            for (int k = i; k < 16; k++) {
                float2 sv = Ss[i][k];
                float2 tv = Tmp[k][j];
                ax += sv.x * tv.x - sv.y * tv.y;
                ay += sv.x * tv.y + sv.y * tv.x;
            }
            Ss[i][16 + j] = make_float2(-ax, -ay);
        }
        __syncthreads();

        // write T (lower triangle = 0)
        for (int t = tid; t < 1024; t += TPB) {
            int r = t >> 5, c = t & 31;
            g_T[t] = (r <= c) ? Ss[r][c] : make_float2(0.f, 0.f);
        }
        __threadfence();
        __syncthreads();
        if (tid == 0) atomicAdd(&g_tready, 1u);

        // reload xs rows 0..63 (clobbered by Gs/Ss/Tmp); rows 64..127 intact
        ((float4*)smem)[tid]       = src[tid];
        ((float4*)smem)[tid + 512] = src[tid + 512];
    } else {
        if (tid == 0) {
            while ((int)(*(volatile unsigned*)&g_tready - rep) < 0) { }
            __threadfence();  // acquire T
        }
        __syncthreads();
    }

    // ================= phase 3: apply  Y = X * T ============================
    {
        float (*Tre)[32] = (float(*)[32])AUX;
        float (*Tim)[32] = (float(*)[32])(AUX + 4096);
        for (int t = tid; t < 1024; t += TPB) {
            float2 v = g_T[t];
            Tre[t >> 5][t & 31] = v.x;
            Tim[t >> 5][t & 31] = v.y;
        }
        __syncthreads();

        int j  = tid & 31;
        int r0 = (tid >> 5) * 8;   // 16 warps x 8 rows = 128 rows

        float ax[8], ay[8];
#pragma unroll
        for (int r = 0; r < 8; r++) { ax[r] = 0.f; ay[r] = 0.f; }

#pragma unroll
        for (int k = 0; k < 32; k += 2) {
            float tr0 = Tre[k][j],     ti0 = Tim[k][j];
            float tr1 = Tre[k + 1][j], ti1 = Tim[k + 1][j];
#pragma unroll
            for (int r = 0; r < 8; r++) {
                float4 a = *(const float4*)&xs[r0 + r][k];   // broadcast LDS.128
                ax[r] += a.x * tr0 - a.y * ti0;
                ay[r] += a.x * ti0 + a.y * tr0;
                ax[r] += a.z * tr1 - a.w * ti1;
                ay[r] += a.z * ti1 + a.w * tr1;
            }
        }

        size_t base = (size_t)blk * TILE + r0;
#pragma unroll
        for (int r = 0; r < 8; r++) {
            y[(base + r) * 32 + j] = make_float2(ax[r], ay[r]);
        }
    }
}

// ---------------------------------------------------------------------------
extern "C" void kernel_launch(void* const* d_in, const int* in_sizes, int n_in,
                              void* d_out, int out_size) {
    const float2* x = (const float2*)d_in[0];
    float2* y = (float2*)d_out;
    (void)in_sizes; (void)n_in; (void)out_size;

    k_all<<<NBLK, TPB>>>(x, y);
}

// round 11
// speedup vs baseline: 1.4756x; 1.0081x over previous
#include <cuda_runtime.h>

#define NBLK 128
#define TPB  512
#define TILE 128
#define NRED 17          // reducer blocks; 17*16 = 272 float4 elements
#define EPSV 1e-10f

__device__ __align__(16) float4 g_partial4[NBLK][272];   // 136 tiles x 2 float4
__device__ __align__(16) float4 g_gram4[272];
__device__ __align__(16) float2 g_T[1024];
__device__ unsigned g_arrive;    // monotonic; +128 per launch
__device__ unsigned g_reddone;   // monotonic; +17  per launch
__device__ unsigned g_tready;    // monotonic; +1   per launch

__device__ __forceinline__ unsigned long long pk2(float lo, float hi) {
    unsigned long long r;
    asm("mov.b64 %0, {%1, %2};" : "=l"(r) : "f"(lo), "f"(hi));
    return r;
}
__device__ __forceinline__ unsigned long long fma2(unsigned long long a,
                                                   unsigned long long b,
                                                   unsigned long long c) {
    unsigned long long d;
    asm("fma.rn.f32x2 %0, %1, %2, %3;" : "=l"(d) : "l"(a), "l"(b), "l"(c));
    return d;
}
__device__ __forceinline__ float2 upk2(unsigned long long v) {
    float lo, hi;
    asm("mov.b64 {%0, %1}, %2;" : "=f"(lo), "=f"(hi) : "l"(v));
    return make_float2(lo, hi);
}

__global__ __launch_bounds__(TPB, 1) void k_all(const float2* __restrict__ x,
                                                float2* __restrict__ y) {
    __shared__ __align__(16) char smem[45056];   // [0,32K) xs | [32K,44K) AUX
    __shared__ float invd[32];
    int tid = threadIdx.x;
    int blk = blockIdx.x;

    float2 (*xs)[32] = (float2(*)[32])smem;      // 128 x 32 float2, resident
    char* AUX = smem + 32768;                    // 12KB: pbuf / Rs / packed T planes

    // ================= phase 1: stage x tile, Hermitian partial Gram ========
    const float4* src = (const float4*)(x + (size_t)blk * TILE * 32);
    {
        float4* dst = (float4*)smem;
#pragma unroll
        for (int t = 0; t < 4; t++) dst[tid + TPB * t] = src[tid + TPB * t];
    }
    __syncthreads();

    {
        int gid = tid >> 8;          // m-group: rows 0-63 / 64-127
        int t8  = tid & 255;
        bool active = (t8 < 136);    // 136 upper-triangular 2x2 tiles
        int i0 = 0, j0 = 0;
        if (active) {
            int tt = t8, ti = 0;
            while (tt >= 16 - ti) { tt -= 16 - ti; ti++; }
            i0 = ti * 2;
            j0 = (ti + tt) * 2;
        }
        float a00x = 0.f, a00y = 0.f, a01x = 0.f, a01y = 0.f;
        float a10x = 0.f, a10y = 0.f, a11x = 0.f, a11y = 0.f;
        if (active) {
            int mbase = gid * 64;
#pragma unroll 8
            for (int mm = 0; mm < 64; mm++) {
                float4 av = *(const float4*)&xs[mbase + mm][i0];
                float4 bv = *(const float4*)&xs[mbase + mm][j0];
                a00x += av.x * bv.x + av.y * bv.y;  a00y += av.x * bv.y - av.y * bv.x;
                a01x += av.x * bv.z + av.y * bv.w;  a01y += av.x * bv.w - av.y * bv.z;
                a10x += av.z * bv.x + av.w * bv.y;  a10y += av.z * bv.y - av.w * bv.x;
                a11x += av.z * bv.z + av.w * bv.w;  a11y += av.z * bv.w - av.w * bv.z;
            }
        }
        float2* P = (float2*)AUX;    // 4 x 136 float2 combine buffer
        if (gid == 1 && active) {
            P[0 * 136 + t8] = make_float2(a00x, a00y);
            P[1 * 136 + t8] = make_float2(a01x, a01y);
            P[2 * 136 + t8] = make_float2(a10x, a10y);
            P[3 * 136 + t8] = make_float2(a11x, a11y);
        }
        __syncthreads();
        if (gid == 0 && active) {
            float2 q;
            q = P[0 * 136 + t8]; a00x += q.x; a00y += q.y;
            q = P[1 * 136 + t8]; a01x += q.x; a01y += q.y;
            q = P[2 * 136 + t8]; a10x += q.x; a10y += q.y;
            q = P[3 * 136 + t8]; a11x += q.x; a11y += q.y;
            float4* out = g_partial4[blk];
            out[t8 * 2]     = make_float4(a00x, a00y, a01x, a01y);
            out[t8 * 2 + 1] = make_float4(a10x, a10y, a11x, a11y);
        }
    }

    __threadfence();          // release partial stores
    __syncthreads();
    unsigned rep = 0;
    if (tid == 0) {
        unsigned v = atomicAdd(&g_arrive, 1u);
        rep = (v >> 7) + 1u;  // launch index; arrive target = rep*128
    }

    // ============ distributed reduce: 17 blocks, warp-per-element ===========
    if (blk < NRED) {
        if (tid == 0) {
            unsigned target = rep << 7;
            while ((int)(*(volatile unsigned*)&g_arrive - target) < 0) { }
            __threadfence();  // acquire partials
        }
        __syncthreads();
        int w = tid >> 5, l = tid & 31;
        int e = blk * 16 + w;                       // 0..271 (17*16 = 272 exactly)
        const float4* gp4 = (const float4*)g_partial4;
        float4 p  = gp4[(size_t)l * 272 + e];
        float4 q1 = gp4[(size_t)(l + 32) * 272 + e];
        float4 q2 = gp4[(size_t)(l + 64) * 272 + e];
        float4 q3 = gp4[(size_t)(l + 96) * 272 + e];
        p.x = ((p.x + q1.x) + q2.x) + q3.x;
        p.y = ((p.y + q1.y) + q2.y) + q3.y;
        p.z = ((p.z + q1.z) + q2.z) + q3.z;
        p.w = ((p.w + q1.w) + q2.w) + q3.w;
#pragma unroll
        for (int off = 16; off > 0; off >>= 1) {
            p.x += __shfl_xor_sync(0xffffffffu, p.x, off);
            p.y += __shfl_xor_sync(0xffffffffu, p.y, off);
            p.z += __shfl_xor_sync(0xffffffffu, p.z, off);
            p.w += __shfl_xor_sync(0xffffffffu, p.w, off);
        }
        if (l == 0) g_gram4[e] = p;
        __threadfence();
        __syncthreads();
        if (tid == 0) atomicAdd(&g_reddone, 1u);
    }

    // ================= phase 2: block 0 solve ===============================
    if (blk == 0) {
        if (tid == 0) {
            unsigned target = rep * NRED;
            while ((int)(*(volatile unsigned*)&g_reddone - target) < 0) { }
            __threadfence();  // acquire g_gram
        }
        __syncthreads();
        // overlays: Gs = xs rows 0..31, Ss = xs rows 32..63, Rs = AUX
        float2 (*Gs)[32] = (float2(*)[32])smem;
        float2 (*Ss)[32] = (float2(*)[32])(smem + 8192);
        float2 (*Rs)[32] = (float2(*)[32])AUX;

        // load + Hermitian mirror G into smem
        if (tid < 136) {
            int tt = tid, ti = 0;
            while (tt >= 16 - ti) { tt -= 16 - ti; ti++; }
            int i0 = ti * 2;
            int j0 = (ti + tt) * 2;
            float4 v0 = g_gram4[tid * 2];
            float4 v1 = g_gram4[tid * 2 + 1];
            Gs[i0][j0]         = make_float2(v0.x, v0.y);
            Gs[i0][j0 + 1]     = make_float2(v0.z, v0.w);
            Gs[i0 + 1][j0]     = make_float2(v1.x, v1.y);
            Gs[i0 + 1][j0 + 1] = make_float2(v1.z, v1.w);
            if (i0 != j0) {
                Gs[j0][i0]         = make_float2(v0.x, -v0.y);
                Gs[j0][i0 + 1]     = make_float2(v1.x, -v1.y);
                Gs[j0 + 1][i0]     = make_float2(v0.z, -v0.w);
                Gs[j0 + 1][i0 + 1] = make_float2(v1.z, -v1.w);
            }
        }
        __syncthreads();

        // Cholesky (upper), warp 0, lane = column k
        if (tid < 32) {
            int k = tid;
            for (int j = 0; j < 32; j++) {
                float2 a = Gs[j][k];
                for (int i = 0; i < j; i++) {
                    float2 rij = Rs[i][j];
                    float2 rik = Rs[i][k];
                    a.x -= rij.x * rik.x + rij.y * rik.y;   // conj(rij)*rik
                    a.y -= rij.x * rik.y - rij.y * rik.x;
                }
                float djj = __shfl_sync(0xffffffffu, a.x, j);
                float rjj = sqrtf(djj + EPSV);
                float inv = 1.0f / rjj;
                float2 out;
                if (k < j)       out = make_float2(0.f, 0.f);
                else if (k == j) out = make_float2(rjj, 0.f);
                else             out = make_float2(a.x * inv, a.y * inv);
                Rs[j][k] = out;
                __syncwarp();
            }
            invd[k] = 1.0f / Rs[k][k].x;
        }
        __syncthreads();

        // Blocked tri-inverse: S11 (lanes 0-15) and S22 (lanes 16-31) in parallel
        if (tid < 32) {
            int half = tid >> 4;
            int j = tid & 15;
            int base = half * 16;
            int gj = base + j;
            Ss[gj][gj] = make_float2(invd[gj], 0.f);
            for (int i = j - 1; i >= 0; i--) {
                int gi = base + i;
                float ax = 0.f, ay = 0.f;
                for (int k = i + 1; k <= j; k++) {
                    int gk = base + k;
                    float2 rv = Rs[gi][gk];
                    float2 sv = Ss[gk][gj];
                    ax += rv.x * sv.x - rv.y * sv.y;
                    ay += rv.x * sv.y + rv.y * sv.x;
                }
                float inv = invd[gi];
                Ss[gi][gj] = make_float2(-ax * inv, -ay * inv);
            }
        }
        __syncthreads();

        // Tmp = R12 * S22   (S22 upper-triangular: k <= j only)
        float2 (*Tmp)[16] = (float2(*)[16])smem;
        if (tid < 256) {
            int i = tid >> 4, j = tid & 15;
            float ax = 0.f, ay = 0.f;
            for (int k = 0; k <= j; k++) {
                float2 rv = Rs[i][16 + k];
                float2 sv = Ss[16 + k][16 + j];
                ax += rv.x * sv.x - rv.y * sv.y;
                ay += rv.x * sv.y + rv.y * sv.x;
            }
            Tmp[i][j] = make_float2(ax, ay);
        }
        __syncthreads();
        // S12 = -S11 * Tmp   (S11 upper-triangular: k >= i)
        if (tid < 256) {
            int i = tid >> 4, j = tid & 15;
            float ax = 0.f, ay = 0.f;
            for (int k = i; k < 16; k++) {
                float2 sv = Ss[i][k];
                float2 tv = Tmp[k][j];
                ax += sv.x * tv.x - sv.y * tv.y;
                ay += sv.x * tv.y + sv.y * tv.x;
            }
            Ss[i][16 + j] = make_float2(-ax, -ay);
        }
        __syncthreads();

        // write T (lower triangle = 0)
        for (int t = tid; t < 1024; t += TPB) {
            int r = t >> 5, c = t & 31;
            g_T[t] = (r <= c) ? Ss[r][c] : make_float2(0.f, 0.f);
        }
        __threadfence();
        __syncthreads();
        if (tid == 0) atomicAdd(&g_tready, 1u);

        // reload xs rows 0..63 (clobbered by Gs/Ss/Tmp); rows 64..127 intact
        ((float4*)smem)[tid]       = src[tid];
        ((float4*)smem)[tid + 512] = src[tid + 512];
    } else {
        if (tid == 0) {
            while ((int)(*(volatile unsigned*)&g_tready - rep) < 0) { }
            __threadfence();  // acquire T
        }
        __syncthreads();
    }

    // ================= phase 3: apply  Y = X * T  (packed f32x2) ============
    {
        unsigned long long (*P1)[32] = (unsigned long long(*)[32])AUX;           // (tr0,tr1)
        unsigned long long (*P2)[32] = (unsigned long long(*)[32])(AUX + 4096);  // (ti0,ti1)
        unsigned long long (*P3)[32] = (unsigned long long(*)[32])(AUX + 8192);  // (-ti0,-ti1)
        {
            int k2 = tid >> 5, jj = tid & 31;   // 512 threads = 16 k-pairs x 32 cols
            float2 v0 = g_T[(2 * k2) * 32 + jj];
            float2 v1 = g_T[(2 * k2 + 1) * 32 + jj];
            P1[k2][jj] = pk2(v0.x, v1.x);
            P2[k2][jj] = pk2(v0.y, v1.y);
            P3[k2][jj] = pk2(-v0.y, -v1.y);
        }
        __syncthreads();

        int j  = tid & 31;
        int r0 = (tid >> 5) * 8;   // 16 warps x 8 rows = 128 rows

        unsigned long long accx[8], accy[8];
        unsigned long long z = pk2(0.f, 0.f);
#pragma unroll
        for (int r = 0; r < 8; r++) { accx[r] = z; accy[r] = z; }

#pragma unroll
        for (int k2 = 0; k2 < 16; k2++) {
            unsigned long long p1 = P1[k2][j];
            unsigned long long p2 = P2[k2][j];
            unsigned long long p3 = P3[k2][j];
#pragma unroll
            for (int r = 0; r < 8; r++) {
                float4 a = *(const float4*)&xs[r0 + r][2 * k2];  // (re0,im0,re1,im1)
                unsigned long long arr = pk2(a.x, a.z);
                unsigned long long aii = pk2(a.y, a.w);
                accx[r] = fma2(arr, p1, accx[r]);
                accx[r] = fma2(aii, p3, accx[r]);
                accy[r] = fma2(arr, p2, accy[r]);
                accy[r] = fma2(aii, p1, accy[r]);
            }
        }

        size_t base = (size_t)blk * TILE + r0;
#pragma unroll
        for (int r = 0; r < 8; r++) {
            float2 fx = upk2(accx[r]);
            float2 fy = upk2(accy[r]);
            y[(base + r) * 32 + j] = make_float2(fx.x + fx.y, fy.x + fy.y);
        }
    }
}

// ---------------------------------------------------------------------------
extern "C" void kernel_launch(void* const* d_in, const int* in_sizes, int n_in,
                              void* d_out, int out_size) {
    const float2* x = (const float2*)d_in[0];
    float2* y = (float2*)d_out;
    (void)in_sizes; (void)n_in; (void)out_size;

    k_all<<<NBLK, TPB>>>(x, y);
}

// round 12
// speedup vs baseline: 1.7469x; 1.1838x over previous
#include <cuda_runtime.h>

#define NBLK 128
#define TPB  512
#define TILE 128
#define NRED 17          // reducer blocks; 17*16 = 272 float4 elements
#define EPSV 1e-10f

__device__ __align__(16) float4 g_partial4[NBLK][272];   // 136 tiles x 2 float4
__device__ __align__(16) float4 g_gram4[272];
__device__ __align__(16) float2 g_T[1024];
__device__ unsigned g_arrive;    // monotonic; +128 per launch
__device__ unsigned g_reddone;   // monotonic; +17  per launch
__device__ unsigned g_tready;    // monotonic; +1   per launch

__device__ __forceinline__ unsigned long long pk2(float lo, float hi) {
    unsigned long long r;
    asm("mov.b64 %0, {%1, %2};" : "=l"(r) : "f"(lo), "f"(hi));
    return r;
}
__device__ __forceinline__ unsigned long long fma2(unsigned long long a,
                                                   unsigned long long b,
                                                   unsigned long long c) {
    unsigned long long d;
    asm("fma.rn.f32x2 %0, %1, %2, %3;" : "=l"(d) : "l"(a), "l"(b), "l"(c));
    return d;
}
__device__ __forceinline__ float2 upk2(unsigned long long v) {
    float lo, hi;
    asm("mov.b64 {%0, %1}, %2;" : "=f"(lo), "=f"(hi) : "l"(v));
    return make_float2(lo, hi);
}

__global__ __launch_bounds__(TPB, 1) void k_all(const float2* __restrict__ x,
                                                float2* __restrict__ y) {
    __shared__ __align__(16) char smem[45056];   // [0,32K) xs | [32K,44K) AUX
    __shared__ float invd[32];
    int tid = threadIdx.x;
    int blk = blockIdx.x;

    float2 (*xs)[32] = (float2(*)[32])smem;      // 128 x 32 float2, resident
    char* AUX = smem + 32768;                    // 12KB: pbuf / Rs / packed T planes

    // ================= phase 1: stage x tile, Hermitian partial Gram ========
    const float4* src = (const float4*)(x + (size_t)blk * TILE * 32);
    {
        float4* dst = (float4*)smem;
#pragma unroll
        for (int t = 0; t < 4; t++) dst[tid + TPB * t] = src[tid + TPB * t];
    }
    __syncthreads();

    {
        int gid = tid >> 8;          // m-group: rows 0-63 / 64-127
        int t8  = tid & 255;
        bool active = (t8 < 136);    // 136 upper-triangular 2x2 tiles
        int i0 = 0, j0 = 0;
        if (active) {
            int tt = t8, ti = 0;
            while (tt >= 16 - ti) { tt -= 16 - ti; ti++; }
            i0 = ti * 2;
            j0 = (ti + tt) * 2;
        }
        float a00x = 0.f, a00y = 0.f, a01x = 0.f, a01y = 0.f;
        float a10x = 0.f, a10y = 0.f, a11x = 0.f, a11y = 0.f;
        if (active) {
            int mbase = gid * 64;
#pragma unroll 8
            for (int mm = 0; mm < 64; mm++) {
                float4 av = *(const float4*)&xs[mbase + mm][i0];
                float4 bv = *(const float4*)&xs[mbase + mm][j0];
                a00x += av.x * bv.x + av.y * bv.y;  a00y += av.x * bv.y - av.y * bv.x;
                a01x += av.x * bv.z + av.y * bv.w;  a01y += av.x * bv.w - av.y * bv.z;
                a10x += av.z * bv.x + av.w * bv.y;  a10y += av.z * bv.y - av.w * bv.x;
                a11x += av.z * bv.z + av.w * bv.w;  a11y += av.z * bv.w - av.w * bv.z;
            }
        }
        float2* P = (float2*)AUX;    // 4 x 136 float2 combine buffer
        if (gid == 1 && active) {
            P[0 * 136 + t8] = make_float2(a00x, a00y);
            P[1 * 136 + t8] = make_float2(a01x, a01y);
            P[2 * 136 + t8] = make_float2(a10x, a10y);
            P[3 * 136 + t8] = make_float2(a11x, a11y);
        }
        __syncthreads();
        if (gid == 0 && active) {
            float2 q;
            q = P[0 * 136 + t8]; a00x += q.x; a00y += q.y;
            q = P[1 * 136 + t8]; a01x += q.x; a01y += q.y;
            q = P[2 * 136 + t8]; a10x += q.x; a10y += q.y;
            q = P[3 * 136 + t8]; a11x += q.x; a11y += q.y;
            float4* out = g_partial4[blk];
            out[t8 * 2]     = make_float4(a00x, a00y, a01x, a01y);
            out[t8 * 2 + 1] = make_float4(a10x, a10y, a11x, a11y);
        }
    }

    __threadfence();          // release partial stores
    __syncthreads();
    unsigned rep = 0;
    if (tid == 0) {
        unsigned v = atomicAdd(&g_arrive, 1u);
        rep = (v >> 7) + 1u;  // launch index; arrive target = rep*128
    }

    // ============ distributed reduce: 17 blocks, warp-per-element ===========
    if (blk < NRED) {
        if (tid == 0) {
            unsigned target = rep << 7;
            while ((int)(*(volatile unsigned*)&g_arrive - target) < 0) { }
            __threadfence();  // acquire partials
        }
        __syncthreads();
        int w = tid >> 5, l = tid & 31;
        int e = blk * 16 + w;                       // 0..271
        const float4* gp4 = (const float4*)g_partial4;
        float4 p  = gp4[(size_t)l * 272 + e];
        float4 q1 = gp4[(size_t)(l + 32) * 272 + e];
        float4 q2 = gp4[(size_t)(l + 64) * 272 + e];
        float4 q3 = gp4[(size_t)(l + 96) * 272 + e];
        p.x = ((p.x + q1.x) + q2.x) + q3.x;
        p.y = ((p.y + q1.y) + q2.y) + q3.y;
        p.z = ((p.z + q1.z) + q2.z) + q3.z;
        p.w = ((p.w + q1.w) + q2.w) + q3.w;
#pragma unroll
        for (int off = 16; off > 0; off >>= 1) {
            p.x += __shfl_xor_sync(0xffffffffu, p.x, off);
            p.y += __shfl_xor_sync(0xffffffffu, p.y, off);
            p.z += __shfl_xor_sync(0xffffffffu, p.z, off);
            p.w += __shfl_xor_sync(0xffffffffu, p.w, off);
        }
        if (l == 0) g_gram4[e] = p;
        __threadfence();
        __syncthreads();
        if (tid == 0) atomicAdd(&g_reddone, 1u);
    }

    // ================= phase 2: block 0 solve ===============================
    if (blk == 0) {
        if (tid == 0) {
            unsigned target = rep * NRED;
            while ((int)(*(volatile unsigned*)&g_reddone - target) < 0) { }
            __threadfence();  // acquire g_gram
        }
        __syncthreads();
        // overlays: Gs = xs rows 0..31, Ss = xs rows 32..63, Rs = AUX
        float2 (*Gs)[32] = (float2(*)[32])smem;
        float2 (*Ss)[32] = (float2(*)[32])(smem + 8192);
        float2 (*Rs)[32] = (float2(*)[32])AUX;

        // load + Hermitian mirror G into smem
        if (tid < 136) {
            int tt = tid, ti = 0;
            while (tt >= 16 - ti) { tt -= 16 - ti; ti++; }
            int i0 = ti * 2;
            int j0 = (ti + tt) * 2;
            float4 v0 = g_gram4[tid * 2];
            float4 v1 = g_gram4[tid * 2 + 1];
            Gs[i0][j0]         = make_float2(v0.x, v0.y);
            Gs[i0][j0 + 1]     = make_float2(v0.z, v0.w);
            Gs[i0 + 1][j0]     = make_float2(v1.x, v1.y);
            Gs[i0 + 1][j0 + 1] = make_float2(v1.z, v1.w);
            if (i0 != j0) {
                Gs[j0][i0]         = make_float2(v0.x, -v0.y);
                Gs[j0][i0 + 1]     = make_float2(v1.x, -v1.y);
                Gs[j0 + 1][i0]     = make_float2(v0.z, -v0.w);
                Gs[j0 + 1][i0 + 1] = make_float2(v1.z, -v1.w);
            }
        }
        __syncthreads();

        // ---- register+shfl Cholesky (upper), warp 0, lane = column k -------
        // Right-looking rank-1 updates; fully unrolled, no LDS in the chain.
        if (tid < 32) {
            int k = tid;
            float2 a[32];
#pragma unroll
            for (int i = 0; i < 32; i++) a[i] = Gs[i][k];
#pragma unroll
            for (int j = 0; j < 32; j++) {
                float d = __shfl_sync(0xffffffffu, a[j].x, j) + EPSV;
                float inv = rsqrtf(d);
                float rjj = d * inv;                       // sqrt(d)
                float rx, ry;
                if (k > j)       { rx = a[j].x * inv; ry = a[j].y * inv; }
                else if (k == j) { rx = rjj; ry = 0.f; invd[j] = inv; }
                else             { rx = 0.f; ry = 0.f; }
                Rs[j][k] = make_float2(rx, ry);
                // a[i] -= conj(R[j][i]) * R[j][k]  for i > j
#pragma unroll
                for (int i = j + 1; i < 32; i++) {
                    float bx = __shfl_sync(0xffffffffu, rx, i);
                    float by = __shfl_sync(0xffffffffu, ry, i);
                    a[i].x -= bx * rx + by * ry;
                    a[i].y -= bx * ry - by * rx;
                }
            }
        }
        __syncthreads();

        // ---- register back-substitution: S11 (lanes 0-15), S22 (16-31) ----
        // Column j's recurrence reads only its own s[] -> registers.
        if (tid < 32) {
            int half = tid >> 4;
            int j = tid & 15;
            int base = half * 16;
            float2 s[16];
#pragma unroll
            for (int i = 15; i >= 0; i--) {
                if (i == j) {
                    s[i] = make_float2(invd[base + i], 0.f);
                } else if (i < j) {
                    float ax = 0.f, ay = 0.f;
#pragma unroll
                    for (int k = i + 1; k < 16; k++) {
                        float2 sv = (k <= j) ? s[k] : make_float2(0.f, 0.f);
                        float2 rv = Rs[base + i][base + k];
                        ax += rv.x * sv.x - rv.y * sv.y;
                        ay += rv.x * sv.y + rv.y * sv.x;
                    }
                    float inv = invd[base + i];
                    s[i] = make_float2(-ax * inv, -ay * inv);
                }
            }
#pragma unroll
            for (int i = 0; i < 16; i++)
                if (i <= j) Ss[base + i][base + j] = s[i];
        }
        __syncthreads();

        // Tmp = R12 * S22   (S22 upper-tri: k <= j; unrolled + predicated)
        float2 (*Tmp)[16] = (float2(*)[16])smem;
        if (tid < 256) {
            int i = tid >> 4, j = tid & 15;
            float ax = 0.f, ay = 0.f;
#pragma unroll
            for (int k = 0; k < 16; k++) {
                if (k <= j) {
                    float2 rv = Rs[i][16 + k];
                    float2 sv = Ss[16 + k][16 + j];
                    ax += rv.x * sv.x - rv.y * sv.y;
                    ay += rv.x * sv.y + rv.y * sv.x;
                }
            }
            Tmp[i][j] = make_float2(ax, ay);
        }
        __syncthreads();
        // S12 = -S11 * Tmp   (S11 upper-tri: k >= i; unrolled + predicated)
        if (tid < 256) {
            int i = tid >> 4, j = tid & 15;
            float ax = 0.f, ay = 0.f;
#pragma unroll
            for (int k = 0; k < 16; k++) {
                if (k >= i) {
                    float2 sv = Ss[i][k];
                    float2 tv = Tmp[k][j];
                    ax += sv.x * tv.x - sv.y * tv.y;
                    ay += sv.x * tv.y + sv.y * tv.x;
                }
            }
            Ss[i][16 + j] = make_float2(-ax, -ay);
        }
        __syncthreads();

        // write T (lower triangle = 0)
        for (int t = tid; t < 1024; t += TPB) {
            int r = t >> 5, c = t & 31;
            g_T[t] = (r <= c) ? Ss[r][c] : make_float2(0.f, 0.f);
        }
        __threadfence();
        __syncthreads();
        if (tid == 0) atomicAdd(&g_tready, 1u);

        // reload xs rows 0..63 (clobbered by Gs/Ss/Tmp); rows 64..127 intact
        ((float4*)smem)[tid]       = src[tid];
        ((float4*)smem)[tid + 512] = src[tid + 512];
    } else {
        if (tid == 0) {
            while ((int)(*(volatile unsigned*)&g_tready - rep) < 0) { }
            __threadfence();  // acquire T
        }
        __syncthreads();
    }

    // ================= phase 3: apply  Y = X * T  (packed f32x2) ============
    {
        unsigned long long (*P1)[32] = (unsigned long long(*)[32])AUX;           // (tr0,tr1)
        unsigned long long (*P2)[32] = (unsigned long long(*)[32])(AUX + 4096);  // (ti0,ti1)
        unsigned long long (*P3)[32] = (unsigned long long(*)[32])(AUX + 8192);  // (-ti0,-ti1)
        {
            int k2 = tid >> 5, jj = tid & 31;   // 512 threads = 16 k-pairs x 32 cols
            float2 v0 = g_T[(2 * k2) * 32 + jj];
            float2 v1 = g_T[(2 * k2 + 1) * 32 + jj];
            P1[k2][jj] = pk2(v0.x, v1.x);
            P2[k2][jj] = pk2(v0.y, v1.y);
            P3[k2][jj] = pk2(-v0.y, -v1.y);
        }
        __syncthreads();

        int j  = tid & 31;
        int r0 = (tid >> 5) * 8;   // 16 warps x 8 rows = 128 rows

        unsigned long long accx[8], accy[8];
        unsigned long long z = pk2(0.f, 0.f);
#pragma unroll
        for (int r = 0; r < 8; r++) { accx[r] = z; accy[r] = z; }

#pragma unroll
        for (int k2 = 0; k2 < 16; k2++) {
            unsigned long long p1 = P1[k2][j];
            unsigned long long p2 = P2[k2][j];
            unsigned long long p3 = P3[k2][j];
#pragma unroll
            for (int r = 0; r < 8; r++) {
                float4 a = *(const float4*)&xs[r0 + r][2 * k2];  // (re0,im0,re1,im1)
                unsigned long long arr = pk2(a.x, a.z);
                unsigned long long aii = pk2(a.y, a.w);
                accx[r] = fma2(arr, p1, accx[r]);
                accx[r] = fma2(aii, p3, accx[r]);
                accy[r] = fma2(arr, p2, accy[r]);
                accy[r] = fma2(aii, p1, accy[r]);
            }
        }

        size_t base = (size_t)blk * TILE + r0;
#pragma unroll
        for (int r = 0; r < 8; r++) {
            float2 fx = upk2(accx[r]);
            float2 fy = upk2(accy[r]);
            y[(base + r) * 32 + j] = make_float2(fx.x + fx.y, fy.x + fy.y);
        }
    }
}

// ---------------------------------------------------------------------------
extern "C" void kernel_launch(void* const* d_in, const int* in_sizes, int n_in,
                              void* d_out, int out_size) {
    const float2* x = (const float2*)d_in[0];
    float2* y = (float2*)d_out;
    (void)in_sizes; (void)n_in; (void)out_size;

    k_all<<<NBLK, TPB>>>(x, y);
}